// round 1
// baseline (speedup 1.0000x reference)
#include <cuda_runtime.h>
#include <math.h>

#define BB 64
#define NN 512
#define DD 128

typedef unsigned long long ull;

__device__ __forceinline__ ull pack2(float lo, float hi){
    ull r; asm("mov.b64 %0, {%1, %2};" : "=l"(r) : "f"(lo), "f"(hi)); return r;
}
__device__ __forceinline__ float2 unpack2(ull v){
    float2 f; asm("mov.b64 {%0, %1}, %2;" : "=f"(f.x), "=f"(f.y) : "l"(v)); return f;
}
__device__ __forceinline__ void fma2(ull &d, ull a, ull b){
    asm("fma.rn.f32x2 %0, %1, %2, %0;" : "+l"(d) : "l"(a), "l"(b));
}

// Scratch (static device globals; no allocation)
__device__ float g_ET[BB*DD*NN];          // E transposed per batch: [b][d][i]  (16 MB)
__device__ float g_z [BB*NN*DD];          // z = E @ W                          (16 MB)
__device__ float g_P [(size_t)BB*NN*NN];  // masked exp weights                 (64 MB)
__device__ float g_el[BB*NN];
__device__ float g_er[BB*NN];
__device__ float g_th[BB];
__device__ float g_cs[BB*4*NN];           // partial colsums per i-tile
__device__ float g_pool[BB*4*DD];         // partial pooled sums per j-tile

// ---------------- transpose: g_ET[b][d][i] = E[b][i][d] ----------------
__global__ void k_T(const float* __restrict__ E){
    __shared__ float t[32][33];
    int b  = blockIdx.z;
    int i0 = blockIdx.x * 32;
    int d0 = blockIdx.y * 32;
    int tx = threadIdx.x, ty = threadIdx.y;   // (32, 8)
    const float* Eb = E + (size_t)b*NN*DD;
    #pragma unroll
    for (int yy = 0; yy < 32; yy += 8)
        t[ty+yy][tx] = Eb[(size_t)(i0+ty+yy)*DD + d0 + tx];
    __syncthreads();
    float* ETb = g_ET + (size_t)b*DD*NN;
    #pragma unroll
    for (int yy = 0; yy < 32; yy += 8)
        ETb[(size_t)(d0+ty+yy)*NN + i0 + tx] = t[tx][ty+yy];
}

// ---------------- thresh[b] = ||sum_i e_i||^2 / N^2 ----------------
__global__ void k_thresh(const float* __restrict__ E){
    int b = blockIdx.x; int t = threadIdx.x;  // 128 threads
    const float* Eb = E + (size_t)b*NN*DD;
    float s = 0.f;
    for (int i = 0; i < NN; i++) s += Eb[(size_t)i*DD + t];
    __shared__ float red[DD];
    red[t] = s * s;
    __syncthreads();
    for (int o = 64; o > 0; o >>= 1){
        if (t < o) red[t] += red[t+o];
        __syncthreads();
    }
    if (t == 0) g_th[b] = red[0] * (1.f / ((float)NN * (float)NN));
}

// ---------------- z = E @ W  (+ fused el/er) ----------------
__global__ void __launch_bounds__(256,2) k_z(const float* __restrict__ W,
                                             const float* __restrict__ attn_l,
                                             const float* __restrict__ attn_r){
    __shared__ float As[32][128];
    __shared__ float Bs[32][128];
    int it = blockIdx.x, b = blockIdx.y;
    int tid = threadIdx.x, tx = tid & 15, ty = tid >> 4;
    const float* ETb = g_ET + (size_t)b*DD*NN;
    int i0 = it * 128;

    ull acc[8][4];
    #pragma unroll
    for (int r = 0; r < 8; r++)
        #pragma unroll
        for (int p = 0; p < 4; p++) acc[r][p] = 0ull;

    #pragma unroll 1
    for (int k0 = 0; k0 < DD; k0 += 32){
        #pragma unroll
        for (int p = 0; p < 4; p++){
            int f = tid + p*256;
            int kk = f >> 5, c = (f & 31) << 2;
            *(float4*)&As[kk][c] = *(const float4*)&ETb[(size_t)(k0+kk)*NN + i0 + c];
            *(float4*)&Bs[kk][c] = *(const float4*)&W  [(size_t)(k0+kk)*DD + c];
        }
        __syncthreads();
        #pragma unroll
        for (int k = 0; k < 32; k++){
            float4 a0 = *(float4*)&As[k][ty*4];
            float4 a1 = *(float4*)&As[k][64 + ty*4];
            float4 b0 = *(float4*)&Bs[k][tx*4];
            float4 b1 = *(float4*)&Bs[k][64 + tx*4];
            ull bp0 = pack2(b0.x,b0.y), bp1 = pack2(b0.z,b0.w);
            ull bp2 = pack2(b1.x,b1.y), bp3 = pack2(b1.z,b1.w);
            float av[8] = {a0.x,a0.y,a0.z,a0.w,a1.x,a1.y,a1.z,a1.w};
            #pragma unroll
            for (int r = 0; r < 8; r++){
                ull s = pack2(av[r], av[r]);
                fma2(acc[r][0], s, bp0); fma2(acc[r][1], s, bp1);
                fma2(acc[r][2], s, bp2); fma2(acc[r][3], s, bp3);
            }
        }
        __syncthreads();
    }

    float al[8], ar[8];
    #pragma unroll
    for (int s = 0; s < 8; s++){
        int d = tx*4 + (s&3) + ((s>>2)<<6);
        al[s] = attn_l[d]; ar[s] = attn_r[d];
    }
    float elp[8], erp[8];
    float* zb = g_z + (size_t)b*NN*DD;
    #pragma unroll
    for (int r = 0; r < 8; r++){
        int i = i0 + ty*4 + (r&3) + ((r>>2)<<6);
        float v[8];
        #pragma unroll
        for (int p = 0; p < 4; p++){ float2 u = unpack2(acc[r][p]); v[p*2] = u.x; v[p*2+1] = u.y; }
        *(float4*)&zb[(size_t)i*DD + tx*4]      = make_float4(v[0],v[1],v[2],v[3]);
        *(float4*)&zb[(size_t)i*DD + 64 + tx*4] = make_float4(v[4],v[5],v[6],v[7]);
        float pe = 0.f, pr = 0.f;
        #pragma unroll
        for (int s = 0; s < 8; s++){ pe += v[s]*al[s]; pr += v[s]*ar[s]; }
        elp[r] = pe; erp[r] = pr;
    }
    __syncthreads();
    float* redl = &As[0][0];
    float* redr = &Bs[0][0];
    #pragma unroll
    for (int r = 0; r < 8; r++){
        int il = ty*4 + (r&3) + ((r>>2)<<6);
        redl[tx*128 + il] = elp[r];
        redr[tx*128 + il] = erp[r];
    }
    __syncthreads();
    if (tid < 128){
        float se = 0.f, sr = 0.f;
        #pragma unroll
        for (int x = 0; x < 16; x++){ se += redl[x*128 + tid]; sr += redr[x*128 + tid]; }
        g_el[b*NN + i0 + tid] = se;
        g_er[b*NN + i0 + tid] = sr;
    }
}

// ---------------- scores -> P (masked exp), partial colsums ----------------
__global__ void __launch_bounds__(256,2) k_scores(){
    __shared__ float As[32][128];
    __shared__ float Bs[32][128];
    int it = blockIdx.x, jt = blockIdx.y, b = blockIdx.z;
    int tid = threadIdx.x, tx = tid & 15, ty = tid >> 4;
    const float* ETb = g_ET + (size_t)b*DD*NN;
    int i0 = it * 128, j0 = jt * 128;

    ull acc[8][4];
    #pragma unroll
    for (int r = 0; r < 8; r++)
        #pragma unroll
        for (int p = 0; p < 4; p++) acc[r][p] = 0ull;

    #pragma unroll 1
    for (int k0 = 0; k0 < DD; k0 += 32){
        #pragma unroll
        for (int p = 0; p < 4; p++){
            int f = tid + p*256;
            int kk = f >> 5, c = (f & 31) << 2;
            *(float4*)&As[kk][c] = *(const float4*)&ETb[(size_t)(k0+kk)*NN + i0 + c];
            *(float4*)&Bs[kk][c] = *(const float4*)&ETb[(size_t)(k0+kk)*NN + j0 + c];
        }
        __syncthreads();
        #pragma unroll
        for (int k = 0; k < 32; k++){
            float4 a0 = *(float4*)&As[k][ty*4];
            float4 a1 = *(float4*)&As[k][64 + ty*4];
            float4 b0 = *(float4*)&Bs[k][tx*4];
            float4 b1 = *(float4*)&Bs[k][64 + tx*4];
            ull bp0 = pack2(b0.x,b0.y), bp1 = pack2(b0.z,b0.w);
            ull bp2 = pack2(b1.x,b1.y), bp3 = pack2(b1.z,b1.w);
            float av[8] = {a0.x,a0.y,a0.z,a0.w,a1.x,a1.y,a1.z,a1.w};
            #pragma unroll
            for (int r = 0; r < 8; r++){
                ull s = pack2(av[r], av[r]);
                fma2(acc[r][0], s, bp0); fma2(acc[r][1], s, bp1);
                fma2(acc[r][2], s, bp2); fma2(acc[r][3], s, bp3);
            }
        }
        __syncthreads();
    }

    float th = g_th[b];
    int gi[8], gj[8]; float eli[8], erj[8];
    #pragma unroll
    for (int r = 0; r < 8; r++){ gi[r] = i0 + ty*4 + (r&3) + ((r>>2)<<6); eli[r] = g_el[b*NN + gi[r]]; }
    #pragma unroll
    for (int s = 0; s < 8; s++){ gj[s] = j0 + tx*4 + (s&3) + ((s>>2)<<6); erj[s] = g_er[b*NN + gj[s]]; }

    float cs[8];
    #pragma unroll
    for (int s = 0; s < 8; s++) cs[s] = 0.f;
    float* Pb = g_P + (size_t)b*NN*NN;
    #pragma unroll
    for (int r = 0; r < 8; r++){
        float v[8];
        #pragma unroll
        for (int p = 0; p < 4; p++){ float2 u = unpack2(acc[r][p]); v[p*2] = u.x; v[p*2+1] = u.y; }
        float pv[8];
        #pragma unroll
        for (int s = 0; s < 8; s++){
            float e = eli[r] + erj[s];
            e = e > 0.f ? e : 0.2f * e;
            float p = (v[s] > th || gi[r] == gj[s]) ? expf(e) : 0.f;
            pv[s] = p; cs[s] += p;
        }
        *(float4*)&Pb[(size_t)gi[r]*NN + j0 + tx*4]      = make_float4(pv[0],pv[1],pv[2],pv[3]);
        *(float4*)&Pb[(size_t)gi[r]*NN + j0 + 64 + tx*4] = make_float4(pv[4],pv[5],pv[6],pv[7]);
    }
    __syncthreads();
    float* red = &As[0][0];
    #pragma unroll
    for (int s = 0; s < 8; s++) red[ty*128 + (gj[s]-j0)] = cs[s];
    __syncthreads();
    if (tid < 128){
        float t = 0.f;
        #pragma unroll
        for (int x = 0; x < 16; x++) t += red[x*128 + tid];
        g_cs[(b*4 + it)*NN + j0 + tid] = t;
    }
}

// ---------------- h = P^T z / colsum; elu(+bias); partial pool ----------------
__global__ void __launch_bounds__(256,2) k_pv(const float* __restrict__ bias){
    __shared__ float As[32][128];   // P tile: [i-k][j]
    __shared__ float Bs[32][128];   // z tile: [i-k][d]
    int jt = blockIdx.x, b = blockIdx.y;
    int tid = threadIdx.x, tx = tid & 15, ty = tid >> 4;
    const float* Pb = g_P + (size_t)b*NN*NN;
    const float* zb = g_z + (size_t)b*NN*DD;
    int j0 = jt * 128;

    ull acc[8][4];
    #pragma unroll
    for (int r = 0; r < 8; r++)
        #pragma unroll
        for (int p = 0; p < 4; p++) acc[r][p] = 0ull;

    #pragma unroll 1
    for (int k0 = 0; k0 < NN; k0 += 32){
        #pragma unroll
        for (int p = 0; p < 4; p++){
            int f = tid + p*256;
            int kk = f >> 5, c = (f & 31) << 2;
            *(float4*)&As[kk][c] = *(const float4*)&Pb[(size_t)(k0+kk)*NN + j0 + c];
            *(float4*)&Bs[kk][c] = *(const float4*)&zb[(size_t)(k0+kk)*DD + c];
        }
        __syncthreads();
        #pragma unroll
        for (int k = 0; k < 32; k++){
            float4 a0 = *(float4*)&As[k][ty*4];
            float4 a1 = *(float4*)&As[k][64 + ty*4];
            float4 b0 = *(float4*)&Bs[k][tx*4];
            float4 b1 = *(float4*)&Bs[k][64 + tx*4];
            ull bp0 = pack2(b0.x,b0.y), bp1 = pack2(b0.z,b0.w);
            ull bp2 = pack2(b1.x,b1.y), bp3 = pack2(b1.z,b1.w);
            float av[8] = {a0.x,a0.y,a0.z,a0.w,a1.x,a1.y,a1.z,a1.w};
            #pragma unroll
            for (int r = 0; r < 8; r++){
                ull s = pack2(av[r], av[r]);
                fma2(acc[r][0], s, bp0); fma2(acc[r][1], s, bp1);
                fma2(acc[r][2], s, bp2); fma2(acc[r][3], s, bp3);
            }
        }
        __syncthreads();
    }

    float inv[8];
    #pragma unroll
    for (int r = 0; r < 8; r++){
        int j = j0 + ty*4 + (r&3) + ((r>>2)<<6);
        float c0 = g_cs[(b*4 + 0)*NN + j] + g_cs[(b*4 + 1)*NN + j]
                 + g_cs[(b*4 + 2)*NN + j] + g_cs[(b*4 + 3)*NN + j];
        inv[r] = 1.f / c0;
    }
    float bi[8]; int dl[8];
    #pragma unroll
    for (int s = 0; s < 8; s++){ dl[s] = tx*4 + (s&3) + ((s>>2)<<6); bi[s] = bias[dl[s]]; }

    float pd[8];
    #pragma unroll
    for (int s = 0; s < 8; s++) pd[s] = 0.f;
    #pragma unroll
    for (int r = 0; r < 8; r++){
        float v[8];
        #pragma unroll
        for (int p = 0; p < 4; p++){ float2 u = unpack2(acc[r][p]); v[p*2] = u.x; v[p*2+1] = u.y; }
        #pragma unroll
        for (int s = 0; s < 8; s++){
            float h = v[s]*inv[r] + bi[s];
            h = h > 0.f ? h : expm1f(h);
            pd[s] += h;
        }
    }
    __syncthreads();
    float* red = &As[0][0];
    #pragma unroll
    for (int s = 0; s < 8; s++) red[ty*128 + dl[s]] = pd[s];
    __syncthreads();
    if (tid < 128){
        float t = 0.f;
        #pragma unroll
        for (int x = 0; x < 16; x++) t += red[x*128 + tid];
        g_pool[(b*4 + jt)*DD + tid] = t;
    }
}

// ---------------- final: mean over nodes ----------------
__global__ void k_out(float* __restrict__ out){
    int b = blockIdx.x, d = threadIdx.x;
    float s = g_pool[(b*4+0)*DD + d] + g_pool[(b*4+1)*DD + d]
            + g_pool[(b*4+2)*DD + d] + g_pool[(b*4+3)*DD + d];
    out[b*DD + d] = s * (1.f / (float)NN);
}

extern "C" void kernel_launch(void* const* d_in, const int* in_sizes, int n_in,
                              void* d_out, int out_size){
    const float* E    = (const float*)d_in[0];
    const float* W    = (const float*)d_in[1];
    const float* al   = (const float*)d_in[2];
    const float* ar   = (const float*)d_in[3];
    const float* bias = (const float*)d_in[4];
    float* out = (float*)d_out;

    k_T     <<<dim3(16,4,64), dim3(32,8)>>>(E);
    k_thresh<<<64, 128>>>(E);
    k_z     <<<dim3(4,64),   256>>>(W, al, ar);
    k_scores<<<dim3(4,4,64), 256>>>();
    k_pv    <<<dim3(4,64),   256>>>(bias);
    k_out   <<<64, 128>>>(out);
}